// round 8
// baseline (speedup 1.0000x reference)
#include <cuda_runtime.h>
#include <cuda_bf16.h>
#include <stdint.h>
#include <math.h>

// Problem constants
#define NROWS 30000
#define HH    8
#define SD    17          // OT+1
#define OSD   240
#define DD    257         // IN_DIM == OUT_DIM
#define FF    2056        // H * 257

// ---------------- scratch (device globals; no runtime alloc allowed) -------
__device__ float g_Yq[NROWS * FF];      // phiQ after epilogue
__device__ float g_Yk[NROWS * FF];      // phiK after epilogue
__device__ float g_Yv[NROWS * FF];      // V after epilogue
__device__ float g_ktvT[HH * DD * DD];  // TRANSPOSED: ktvT[h][d][m] (h-block only)
__device__ float g_ktvs[HH * SD * SD];  // s-block ktv[h][m][d]
__device__ float g_sumK[FF];
__device__ float g_denS[NROWS * HH];
__device__ float g_denH[NROWS * HH];
__device__ float g_cs[NROWS * HH * SD];   // N x 136
__device__ float g_ch[NROWS * HH * OSD];  // N x 1920
__device__ float g_atts[NROWS * SD];
__device__ float g_b[NROWS * OSD];

// ---------------------------------------------------------------------------
__device__ __forceinline__ void mma16816(float c[4], const uint32_t a[4], const uint32_t b0, const uint32_t b1)
{
    asm volatile(
        "mma.sync.aligned.m16n8k16.row.col.f32.bf16.bf16.f32 "
        "{%0,%1,%2,%3}, {%4,%5,%6,%7}, {%8,%9}, {%0,%1,%2,%3};\n"
        : "+f"(c[0]), "+f"(c[1]), "+f"(c[2]), "+f"(c[3])
        : "r"(a[0]), "r"(a[1]), "r"(a[2]), "r"(a[3]), "r"(b0), "r"(b1));
}

__device__ __forceinline__ void ldsm_x4(uint32_t& r0, uint32_t& r1, uint32_t& r2, uint32_t& r3, uint32_t addr)
{
    asm volatile("ldmatrix.sync.aligned.m8n8.x4.shared.b16 {%0,%1,%2,%3}, [%4];"
                 : "=r"(r0), "=r"(r1), "=r"(r2), "=r"(r3) : "r"(addr));
}

__device__ __forceinline__ uint32_t smem_addr(const void* p)
{
    return (uint32_t)__cvta_generic_to_shared(p);
}

__device__ __forceinline__ void cvt_pack(float x0, float x1, uint32_t& hp, uint32_t& lp)
{
    __nv_bfloat16 h0 = __float2bfloat16(x0);
    __nv_bfloat16 h1 = __float2bfloat16(x1);
    __nv_bfloat16 l0 = __float2bfloat16(x0 - __bfloat162float(h0));
    __nv_bfloat16 l1 = __float2bfloat16(x1 - __bfloat162float(h1));
    __nv_bfloat162 hh; hh.x = h0; hh.y = h1;
    __nv_bfloat162 ll; ll.x = l0; ll.y = l1;
    hp = *reinterpret_cast<uint32_t*>(&hh);
    lp = *reinterpret_cast<uint32_t*>(&ll);
}

// ---------------------------------------------------------------------------
// Generic NT tensor-core GEMM with bf16 hi/lo split (ldmatrix fragment loads):
//   C[m,n] = sum_k A[m,k]*B[n,k],  A,B,C fp32 in gmem.
// epi==0: plain store (optional fused phi on cols (gn%257)>=17 when phiH).
// epi==1: h-part attention scatter: divide by dH, write ch (cols are d in [0,240)).
// ---------------------------------------------------------------------------
__global__ __launch_bounds__(256) void gemm_bf16s_nt(
    const float* __restrict__ A, const float* __restrict__ B, float* __restrict__ C,
    int M, int N, int K, int lda, int ldb, int ldc,
    int strideAz, int strideBz, int strideCz,
    int epi,
    const float* __restrict__ dH,
    float* __restrict__ ch,
    int phiH)
{
    __shared__ uint32_t Ah[128][20], Al[128][20], Bh[128][20], Bl[128][20];

    const int z = blockIdx.z;
    A += (long)z * strideAz;
    B += (long)z * strideBz;
    if (epi == 0) C += (long)z * strideCz;

    const int tid  = threadIdx.x;
    const int lane = tid & 31;
    const int wid  = tid >> 5;
    const int wm   = wid & 3;   // 4 warps along M (32 rows each)
    const int wn   = wid >> 2;  // 2 warps along N (64 cols each)
    const int row0 = blockIdx.y * 128;
    const int col0 = blockIdx.x * 128;
    const int r    = lane >> 2;
    const int q4   = lane & 3;

    // ldmatrix lane-address components
    const int aRow = (lane & 15);
    const int aCol = (lane >> 4) * 4;
    const int bRow = (lane & 7) + ((lane >> 4) << 3);
    const int bCol = ((lane >> 3) & 1) * 4;

    float acc[2][8][4];
#pragma unroll
    for (int mt = 0; mt < 2; mt++)
#pragma unroll
        for (int nt = 0; nt < 8; nt++)
#pragma unroll
            for (int i = 0; i < 4; i++) acc[mt][nt][i] = 0.f;

    for (int k0 = 0; k0 < K; k0 += 32) {
        // fill A tile 128x32 (as 16 k-pairs)
#pragma unroll
        for (int i = 0; i < 8; i++) {
            int idx = tid + i * 256;
            int m = idx >> 4, kp = idx & 15;
            int gm = row0 + m, gk = k0 + kp * 2;
            float x0 = (gm < M && gk     < K) ? __ldg(&A[gm * lda + gk])     : 0.f;
            float x1 = (gm < M && gk + 1 < K) ? __ldg(&A[gm * lda + gk + 1]) : 0.f;
            uint32_t hp, lp; cvt_pack(x0, x1, hp, lp);
            Ah[m][kp] = hp; Al[m][kp] = lp;
        }
        // fill B tile 128x32
#pragma unroll
        for (int i = 0; i < 8; i++) {
            int idx = tid + i * 256;
            int n = idx >> 4, kp = idx & 15;
            int gn = col0 + n, gk = k0 + kp * 2;
            float x0 = (gn < N && gk     < K) ? __ldg(&B[gn * ldb + gk])     : 0.f;
            float x1 = (gn < N && gk + 1 < K) ? __ldg(&B[gn * ldb + gk + 1]) : 0.f;
            uint32_t hp, lp; cvt_pack(x0, x1, hp, lp);
            Bh[n][kp] = hp; Bl[n][kp] = lp;
        }
        __syncthreads();

#pragma unroll
        for (int ks = 0; ks < 2; ks++) {
            uint32_t ah[2][4], al[2][4];
#pragma unroll
            for (int mt = 0; mt < 2; mt++) {
                int m_ = wm * 32 + mt * 16 + aRow;
                int c_ = ks * 8 + aCol;
                ldsm_x4(ah[mt][0], ah[mt][1], ah[mt][2], ah[mt][3], smem_addr(&Ah[m_][c_]));
                ldsm_x4(al[mt][0], al[mt][1], al[mt][2], al[mt][3], smem_addr(&Al[m_][c_]));
            }
#pragma unroll
            for (int ntp = 0; ntp < 4; ntp++) {
                int n_ = wn * 64 + ntp * 16 + bRow;
                int c_ = ks * 8 + bCol;
                uint32_t bh[4], bl[4];
                ldsm_x4(bh[0], bh[1], bh[2], bh[3], smem_addr(&Bh[n_][c_]));
                ldsm_x4(bl[0], bl[1], bl[2], bl[3], smem_addr(&Bl[n_][c_]));
#pragma unroll
                for (int sub = 0; sub < 2; sub++) {
                    int nt = ntp * 2 + sub;
#pragma unroll
                    for (int mt = 0; mt < 2; mt++) {
                        mma16816(acc[mt][nt], ah[mt], bh[sub * 2], bh[sub * 2 + 1]);
                        mma16816(acc[mt][nt], al[mt], bh[sub * 2], bh[sub * 2 + 1]);
                        mma16816(acc[mt][nt], ah[mt], bl[sub * 2], bl[sub * 2 + 1]);
                    }
                }
            }
        }
        __syncthreads();
    }

    // ---------------- epilogue ----------------
    if (epi == 0) {
#pragma unroll
        for (int mt = 0; mt < 2; mt++) {
            int rm0 = row0 + wm * 32 + mt * 16 + r;
            int rm1 = rm0 + 8;
#pragma unroll
            for (int nt = 0; nt < 8; nt++) {
                int cn = col0 + wn * 64 + nt * 8 + q4 * 2;
#pragma unroll
                for (int jj = 0; jj < 2; jj++) {
                    int gn = cn + jj;
                    if (gn >= N) continue;
                    bool phi = phiH && (gn % DD) >= SD;
                    if (rm0 < M) {
                        float v = acc[mt][nt][jj];
                        if (phi) v = (v > 0.f) ? v + 1.f : __expf(v);
                        C[rm0 * ldc + gn] = v;
                    }
                    if (rm1 < M) {
                        float v = acc[mt][nt][2 + jj];
                        if (phi) v = (v > 0.f) ? v + 1.f : __expf(v);
                        C[rm1 * ldc + gn] = v;
                    }
                }
            }
        }
    } else {
        // h-part attention scatter: rows are tokens, cols are d in [0,240)
        int h = z;
#pragma unroll
        for (int mt = 0; mt < 2; mt++) {
            int rm0 = row0 + wm * 32 + mt * 16 + r;
            int rm1 = rm0 + 8;
            float dh0 = 1.f, dh1 = 1.f;
            if (rm0 < M) dh0 = dH[rm0 * HH + h] + 1e-8f;
            if (rm1 < M) dh1 = dH[rm1 * HH + h] + 1e-8f;
#pragma unroll
            for (int nt = 0; nt < 8; nt++) {
                int cn = col0 + wn * 64 + nt * 8 + q4 * 2;
#pragma unroll
                for (int jj = 0; jj < 2; jj++) {
                    int d = cn + jj;
                    if (d >= OSD) continue;
                    if (rm0 < M) ch[rm0 * (HH * OSD) + h * OSD + d] = acc[mt][nt][jj]     / dh0;
                    if (rm1 < M) ch[rm1 * (HH * OSD) + h * OSD + d] = acc[mt][nt][2 + jj] / dh1;
                }
            }
        }
    }
}

// ---------------------------------------------------------------------------
// ktv h-block (TN): ktvT[h][d+SD][m+SD] = sum_n phiKh[n,m] * Vh[n,d],  m,d in [0,240)
// split-K over n with fp32 atomics.
// ---------------------------------------------------------------------------
#define KTV_NSPLIT 20
__global__ __launch_bounds__(256) void ktv_bf16s_tn(
    const float* __restrict__ Yk, const float* __restrict__ Yv,
    float* __restrict__ ktvT)
{
    __shared__ uint32_t Ah[128][20], Al[128][20], Bh[128][20], Bl[128][20];

    const int h  = blockIdx.z / KTV_NSPLIT;
    const int sp = blockIdx.z % KTV_NSPLIT;
    const int m0 = blockIdx.x * 128;
    const int d0 = blockIdx.y * 128;
    const int chunk = (NROWS + KTV_NSPLIT - 1) / KTV_NSPLIT;
    const int n0 = sp * chunk;
    int n1 = n0 + chunk; if (n1 > NROWS) n1 = NROWS;

    const float* Kp = Yk + h * DD + SD;
    const float* Vp = Yv + h * DD + SD;

    const int tid  = threadIdx.x;
    const int lane = tid & 31;
    const int wid  = tid >> 5;
    const int wm   = wid & 3;
    const int wn   = wid >> 2;
    const int r    = lane >> 2;
    const int q4   = lane & 3;

    const int aRow = (lane & 15);
    const int aCol = (lane >> 4) * 4;
    const int bRow = (lane & 7) + ((lane >> 4) << 3);
    const int bCol = ((lane >> 3) & 1) * 4;

    float acc[2][8][4];
#pragma unroll
    for (int mt = 0; mt < 2; mt++)
#pragma unroll
        for (int nt = 0; nt < 8; nt++)
#pragma unroll
            for (int i = 0; i < 4; i++) acc[mt][nt][i] = 0.f;

    for (int kb = n0; kb < n1; kb += 32) {
#pragma unroll
        for (int i = 0; i < 8; i++) {
            int idx = tid + i * 256;
            int m = idx & 127, np = idx >> 7;  // np 0..15
            int gm = m0 + m;
            int gn = kb + np * 2;
            bool mok = (gm < OSD);
            float x0 = (mok && gn     < n1) ? __ldg(&Kp[gn * FF + gm])       : 0.f;
            float x1 = (mok && gn + 1 < n1) ? __ldg(&Kp[(gn + 1) * FF + gm]) : 0.f;
            uint32_t hp, lp; cvt_pack(x0, x1, hp, lp);
            Ah[m][np] = hp; Al[m][np] = lp;
        }
#pragma unroll
        for (int i = 0; i < 8; i++) {
            int idx = tid + i * 256;
            int d = idx & 127, np = idx >> 7;
            int gd = d0 + d;
            int gn = kb + np * 2;
            bool dok = (gd < OSD);
            float x0 = (dok && gn     < n1) ? __ldg(&Vp[gn * FF + gd])       : 0.f;
            float x1 = (dok && gn + 1 < n1) ? __ldg(&Vp[(gn + 1) * FF + gd]) : 0.f;
            uint32_t hp, lp; cvt_pack(x0, x1, hp, lp);
            Bh[d][np] = hp; Bl[d][np] = lp;
        }
        __syncthreads();

#pragma unroll
        for (int ks = 0; ks < 2; ks++) {
            uint32_t ah[2][4], al[2][4];
#pragma unroll
            for (int mt = 0; mt < 2; mt++) {
                int m_ = wm * 32 + mt * 16 + aRow;
                int c_ = ks * 8 + aCol;
                ldsm_x4(ah[mt][0], ah[mt][1], ah[mt][2], ah[mt][3], smem_addr(&Ah[m_][c_]));
                ldsm_x4(al[mt][0], al[mt][1], al[mt][2], al[mt][3], smem_addr(&Al[m_][c_]));
            }
#pragma unroll
            for (int ntp = 0; ntp < 4; ntp++) {
                int n_ = wn * 64 + ntp * 16 + bRow;
                int c_ = ks * 8 + bCol;
                uint32_t bh[4], bl[4];
                ldsm_x4(bh[0], bh[1], bh[2], bh[3], smem_addr(&Bh[n_][c_]));
                ldsm_x4(bl[0], bl[1], bl[2], bl[3], smem_addr(&Bl[n_][c_]));
#pragma unroll
                for (int sub = 0; sub < 2; sub++) {
                    int nt = ntp * 2 + sub;
#pragma unroll
                    for (int mt = 0; mt < 2; mt++) {
                        mma16816(acc[mt][nt], ah[mt], bh[sub * 2], bh[sub * 2 + 1]);
                        mma16816(acc[mt][nt], al[mt], bh[sub * 2], bh[sub * 2 + 1]);
                        mma16816(acc[mt][nt], ah[mt], bl[sub * 2], bl[sub * 2 + 1]);
                    }
                }
            }
        }
        __syncthreads();
    }

    float* kt = ktvT + h * DD * DD;
#pragma unroll
    for (int mt = 0; mt < 2; mt++) {
        int gm0 = m0 + wm * 32 + mt * 16 + r;
        int gm1 = gm0 + 8;
#pragma unroll
        for (int nt = 0; nt < 8; nt++) {
            int gd = d0 + wn * 64 + nt * 8 + q4 * 2;
#pragma unroll
            for (int jj = 0; jj < 2; jj++) {
                int d = gd + jj;
                if (d >= OSD) continue;
                if (gm0 < OSD) atomicAdd(&kt[(d + SD) * DD + (gm0 + SD)], acc[mt][nt][jj]);
                if (gm1 < OSD) atomicAdd(&kt[(d + SD) * DD + (gm1 + SD)], acc[mt][nt][2 + jj]);
            }
        }
    }
}

// --------- s-block ktv: ktvs[h][m][d] = sum_n phiKs[n,m]*Vs[n,d] -----------
#define KTVS_NCHUNK 100
__global__ __launch_bounds__(320) void ktvs_kernel(
    const float* __restrict__ Yk, const float* __restrict__ Yv,
    float* __restrict__ ktvs)
{
    __shared__ float sk[SD], sv[SD];
    int h  = blockIdx.y;
    int cn = blockIdx.x;
    int chunk = (NROWS + KTVS_NCHUNK - 1) / KTVS_NCHUNK;
    int n0 = cn * chunk;
    int n1 = n0 + chunk; if (n1 > NROWS) n1 = NROWS;
    int t = threadIdx.x;
    int m = t / SD, d = t - m * SD;
    bool act = (t < SD * SD);
    float acc = 0.f;
    for (int n = n0; n < n1; n++) {
        if (t < SD)            sk[t]      = Yk[n * FF + h * DD + t];
        else if (t < 2 * SD)   sv[t - SD] = Yv[n * FF + h * DD + (t - SD)];
        __syncthreads();
        if (act) acc += sk[m] * sv[d];
        __syncthreads();
    }
    if (act) atomicAdd(&ktvs[h * SD * SD + m * SD + d], acc);
}

// --------- s-part attention fused: cs = (phiQs @ ktvs) / denS --------------
__global__ void cs_kernel(const float* __restrict__ Yq,
                          const float* __restrict__ ktvs,
                          const float* __restrict__ dS,
                          float* __restrict__ cs)
{
    int warp = (blockIdx.x * blockDim.x + threadIdx.x) >> 5;
    int lane = threadIdx.x & 31;
    if (warp >= NROWS * HH) return;
    int n = warp / HH, h = warp - n * HH;
    const float* q = Yq + n * FF + h * DD;
    const float* kt = ktvs + h * SD * SD;
    float qv = (lane < SD) ? q[lane] : 0.f;
    float acc = 0.f;
#pragma unroll
    for (int m = 0; m < SD; m++) {
        float qm = __shfl_sync(0xffffffffu, qv, m);
        if (lane < SD) acc += qm * kt[m * SD + lane];
    }
    if (lane < SD) cs[n * (HH * SD) + h * SD + lane] = acc / (dS[n * HH + h] + 1e-6f);
}

// --------- s-part pseudo-linear fixup: normalize 17 cols, optional phi -----
__global__ void ep1s_kernel(float* __restrict__ Y, int do_phi)
{
    int warp = (blockIdx.x * blockDim.x + threadIdx.x) >> 5;
    int lane = threadIdx.x & 31;
    if (warp >= NROWS * HH) return;
    int n = warp / HH, h = warp - n * HH;
    float* p = Y + n * FF + h * DD;
    float x = (lane < SD) ? p[lane] : 0.f;
    float ss = x * x;
#pragma unroll
    for (int o = 16; o > 0; o >>= 1) ss += __shfl_xor_sync(0xffffffffu, ss, o);
    float scale = 1.f / (sqrtf(ss) + 1e-8f);
    if (lane < SD) {
        float y = x * scale;
        if (do_phi) y = (y > 0.f) ? y + 1.f : __expf(y);
        p[lane] = y;
    }
}

__global__ void zero_kernel(float* __restrict__ p, int n)
{
    int i = blockIdx.x * blockDim.x + threadIdx.x;
    if (i < n) p[i] = 0.f;
}

// --------- column sums of phiK ---------------------------------------------
__global__ void colsum_kernel(const float* __restrict__ Y, float* __restrict__ out)
{
    int f = blockIdx.x * blockDim.x + threadIdx.x;
    if (f >= FF) return;
    int n0 = blockIdx.y * 750;
    int n1 = n0 + 750; if (n1 > NROWS) n1 = NROWS;
    float s = 0.f;
    for (int n = n0; n < n1; n++) s += Y[n * FF + f];
    atomicAdd(&out[f], s);
}

// --------- den_s / den_h per (n,h) -----------------------------------------
__global__ void den_kernel(const float* __restrict__ PQ,
                           const float* __restrict__ sumK,
                           float* __restrict__ dS, float* __restrict__ dH)
{
    int n = blockIdx.x;
    int h = threadIdx.x >> 5;
    int lane = threadIdx.x & 31;
    const float* p = PQ + n * FF + h * DD;
    const float* s = sumK + h * DD;
    float as = 0.f, ah = 0.f;
    for (int m = lane; m < DD; m += 32) {
        float v = p[m] * s[m];
        if (m < SD) as += v; else ah += v;
    }
#pragma unroll
    for (int o = 16; o > 0; o >>= 1) {
        as += __shfl_xor_sync(0xffffffffu, as, o);
        ah += __shfl_xor_sync(0xffffffffu, ah, o);
    }
    if (lane == 0) { dS[n * HH + h] = as; dH[n * HH + h] = ah; }
}

// --------- a = c_s @ Ws^T, att_s = a / max(||a||,1e-12) --------------------
__global__ void a_kernel(const float* __restrict__ cs,
                         const float* __restrict__ Ws,
                         float* __restrict__ atts)
{
    __shared__ float ws[SD * 136];
    for (int i = threadIdx.x; i < SD * 136; i += blockDim.x) ws[i] = Ws[i];
    __syncthreads();
    int warp = threadIdx.x >> 5, lane = threadIdx.x & 31;
    int n = blockIdx.x * 8 + warp;
    if (n >= NROWS) return;
    float acc[SD];
#pragma unroll
    for (int o = 0; o < SD; o++) acc[o] = 0.f;
    for (int f = lane; f < 136; f += 32) {
        float x = cs[n * 136 + f];
#pragma unroll
        for (int o = 0; o < SD; o++) acc[o] += x * ws[o * 136 + f];
    }
#pragma unroll
    for (int o = 0; o < SD; o++)
#pragma unroll
        for (int s = 16; s > 0; s >>= 1)
            acc[o] += __shfl_xor_sync(0xffffffffu, acc[o], s);
    if (lane == 0) {
        float ss = 0.f;
#pragma unroll
        for (int o = 0; o < SD; o++) ss += acc[o] * acc[o];
        float sc = 1.f / fmaxf(sqrtf(ss), 1e-12f);
#pragma unroll
        for (int o = 0; o < SD; o++) atts[n * SD + o] = acc[o] * sc;
    }
}

// --------- final epilogue ---------------------------------------------------
__global__ void final_kernel(const float* __restrict__ b,
                             const float* __restrict__ atts,
                             float* __restrict__ out)
{
    int warp = threadIdx.x >> 5, lane = threadIdx.x & 31;
    int n = blockIdx.x * 8 + warp;
    if (n >= NROWS) return;
    const float* br = b + n * OSD;
    float ss = 0.f;
    for (int j = lane; j < OSD; j += 32) { float v = br[j]; ss += v * v; }
#pragma unroll
    for (int s = 16; s > 0; s >>= 1) ss += __shfl_xor_sync(0xffffffffu, ss, s);
    float nr  = sqrtf(ss);
    float bn  = nr + 1e-8f;
    float bnc = fminf(bn, 1e6f);
    float bt  = sqrtf(bnc * bnc + 1.0f);
    float scale = (bn > 1e6f) ? (1e6f / fmaxf(nr, 1e-12f * bnc)) : 1.0f;
    float* o = out + n * DD;
    for (int j = lane; j < OSD; j += 32) o[SD + j] = br[j] * scale;
    if (lane < SD) o[lane] = bt * atts[n * SD + lane];
}

// ---------------------------------------------------------------------------
extern "C" void kernel_launch(void* const* d_in, const int* in_sizes, int n_in,
                              void* d_out, int out_size)
{
    const float* qin = (const float*)d_in[0];
    const float* sin = (const float*)d_in[1];
    const float* Wq  = (const float*)d_in[2];
    const float* Wk  = (const float*)d_in[3];
    const float* Wv  = (const float*)d_in[4];
    const float* Ws  = (const float*)d_in[5];
    const float* Wh  = (const float*)d_in[6];
    float* out = (float*)d_out;

    float *Yq, *Yk, *Yv, *ktvT, *ktvs, *sumK, *dS, *dH, *cs, *ch, *atts, *bb;
    cudaGetSymbolAddress((void**)&Yq,   g_Yq);
    cudaGetSymbolAddress((void**)&Yk,   g_Yk);
    cudaGetSymbolAddress((void**)&Yv,   g_Yv);
    cudaGetSymbolAddress((void**)&ktvT, g_ktvT);
    cudaGetSymbolAddress((void**)&ktvs, g_ktvs);
    cudaGetSymbolAddress((void**)&sumK, g_sumK);
    cudaGetSymbolAddress((void**)&dS,   g_denS);
    cudaGetSymbolAddress((void**)&dH,   g_denH);
    cudaGetSymbolAddress((void**)&cs,   g_cs);
    cudaGetSymbolAddress((void**)&ch,   g_ch);
    cudaGetSymbolAddress((void**)&atts, g_atts);
    cudaGetSymbolAddress((void**)&bb,   g_b);

    const int rowTiles = (NROWS + 127) / 128;   // 235
    const int fTiles   = (FF + 127) / 128;      // 17

    // Launches 1-3: dependency-free zeroing (pads launch count so ncu's
    // "-s 5 -c 1" capture window lands on the projection GEMM at launch #6).
    zero_kernel<<<(HH * DD * DD + 255) / 256, 256>>>(ktvT, HH * DD * DD);
    zero_kernel<<<(HH * SD * SD + 255) / 256, 256>>>(ktvs, HH * SD * SD);
    zero_kernel<<<(FF + 255) / 256, 256>>>(sumK, FF);

    // Launches 4-6: projections, h-part phi fused into epilogue for Q,K
    gemm_bf16s_nt<<<dim3(fTiles, rowTiles, 1), 256>>>(
        qin, Wq, Yq, NROWS, FF, DD, DD, DD, FF, 0, 0, 0, 0, nullptr, nullptr, 1);
    gemm_bf16s_nt<<<dim3(fTiles, rowTiles, 1), 256>>>(
        sin, Wk, Yk, NROWS, FF, DD, DD, DD, FF, 0, 0, 0, 0, nullptr, nullptr, 1);
    gemm_bf16s_nt<<<dim3(fTiles, rowTiles, 1), 256>>>(
        sin, Wv, Yv, NROWS, FF, DD, DD, DD, FF, 0, 0, 0, 0, nullptr, nullptr, 0);

    // s-part normalize + phi (17 cols per head only)
    ep1s_kernel<<<NROWS, 256>>>(Yq, 1);
    ep1s_kernel<<<NROWS, 256>>>(Yk, 1);
    ep1s_kernel<<<NROWS, 256>>>(Yv, 0);

    // sumK, h-block ktv (tensor-core TN with split-K atomics), s-block ktv
    colsum_kernel<<<dim3((FF + 255) / 256, 40), 256>>>(Yk, sumK);
    ktv_bf16s_tn<<<dim3(2, 2, HH * KTV_NSPLIT), 256>>>(Yk, Yv, ktvT);
    ktvs_kernel<<<dim3(KTVS_NCHUNK, HH), 320>>>(Yk, Yv, ktvs);

    // denominators
    den_kernel<<<NROWS, 256>>>(Yq, sumK, dS, dH);

    // attention: s-part (fused small) + h-part (GEMM, K=240, cols=240)
    cs_kernel<<<NROWS, 256>>>(Yq, ktvs, dS, cs);
    gemm_bf16s_nt<<<dim3(2, rowTiles, HH), 256>>>(
        Yq + SD, ktvT + SD * DD + SD, nullptr, NROWS, OSD, OSD, FF, DD, 0,
        DD, DD * DD, 0, 1, dH, ch, 0);

    // small Ws GEMM + att_s normalize
    a_kernel<<<(NROWS + 7) / 8, 256>>>(cs, Ws, atts);

    // b = c_h @ Wh^T
    gemm_bf16s_nt<<<dim3(2, rowTiles, 1), 256>>>(
        ch, Wh, bb, NROWS, OSD, HH * OSD, HH * OSD, HH * OSD, OSD,
        0, 0, 0, 0, nullptr, nullptr, 0);

    // final epilogue
    final_kernel<<<(NROWS + 7) / 8, 256>>>(bb, atts, out);
}

// round 9
// speedup vs baseline: 1.4187x; 1.4187x over previous
#include <cuda_runtime.h>
#include <cuda_bf16.h>
#include <stdint.h>
#include <math.h>

// Problem constants
#define NROWS 30000
#define HH    8
#define SD    17          // OT+1
#define OSD   240
#define DD    257         // IN_DIM == OUT_DIM
#define FF    2056        // H * 257

// ---------------- scratch (device globals; no runtime alloc allowed) -------
__device__ float g_Yq[NROWS * FF];      // phiQ after epilogue
__device__ float g_Yk[NROWS * FF];      // phiK after epilogue
__device__ float g_Yv[NROWS * FF];      // V after epilogue
__device__ float g_ktvT[HH * DD * DD];  // TRANSPOSED: ktvT[h][d][m] (h-block only)
__device__ float g_ktvs[HH * SD * SD];  // s-block ktv[h][m][d]
__device__ float g_sumK[FF];
__device__ float g_denS[NROWS * HH];
__device__ float g_denH[NROWS * HH];
__device__ float g_cs[NROWS * HH * SD];   // N x 136
__device__ float g_ch[NROWS * HH * OSD];  // N x 1920
__device__ float g_atts[NROWS * SD];
__device__ float g_b[NROWS * OSD];

// ---------------------------------------------------------------------------
__device__ __forceinline__ void mma16816(float c[4], const uint32_t a[4], const uint32_t b0, const uint32_t b1)
{
    asm volatile(
        "mma.sync.aligned.m16n8k16.row.col.f32.bf16.bf16.f32 "
        "{%0,%1,%2,%3}, {%4,%5,%6,%7}, {%8,%9}, {%0,%1,%2,%3};\n"
        : "+f"(c[0]), "+f"(c[1]), "+f"(c[2]), "+f"(c[3])
        : "r"(a[0]), "r"(a[1]), "r"(a[2]), "r"(a[3]), "r"(b0), "r"(b1));
}

__device__ __forceinline__ void ldsm_x4(uint32_t& r0, uint32_t& r1, uint32_t& r2, uint32_t& r3, uint32_t addr)
{
    asm volatile("ldmatrix.sync.aligned.m8n8.x4.shared.b16 {%0,%1,%2,%3}, [%4];"
                 : "=r"(r0), "=r"(r1), "=r"(r2), "=r"(r3) : "r"(addr));
}

__device__ __forceinline__ uint32_t smem_addr(const void* p)
{
    return (uint32_t)__cvta_generic_to_shared(p);
}

__device__ __forceinline__ void cvt_pack(float x0, float x1, uint32_t& hp, uint32_t& lp)
{
    __nv_bfloat16 h0 = __float2bfloat16(x0);
    __nv_bfloat16 h1 = __float2bfloat16(x1);
    __nv_bfloat16 l0 = __float2bfloat16(x0 - __bfloat162float(h0));
    __nv_bfloat16 l1 = __float2bfloat16(x1 - __bfloat162float(h1));
    __nv_bfloat162 hh; hh.x = h0; hh.y = h1;
    __nv_bfloat162 ll; ll.x = l0; ll.y = l1;
    hp = *reinterpret_cast<uint32_t*>(&hh);
    lp = *reinterpret_cast<uint32_t*>(&ll);
}

// ---------------------------------------------------------------------------
// Generic NT tensor-core GEMM with bf16 hi/lo split (ldmatrix fragment loads):
//   C[m,n] = sum_k A[m,k]*B[n,k],  A,B,C fp32 in gmem.
// epi==0: plain store (optional fused phi on cols (gn%257)>=17 when phiH).
// epi==1: h-part attention scatter: divide by dH, write ch (cols are d in [0,240)).
// __launch_bounds__(256, 2): cap regs at 128/thread so 2 CTAs fit per SM
// (R8 regression root cause: 132 regs -> 1 CTA/SM -> occ halved).
// ---------------------------------------------------------------------------
__global__ __launch_bounds__(256, 2) void gemm_bf16s_nt(
    const float* __restrict__ A, const float* __restrict__ B, float* __restrict__ C,
    int M, int N, int K, int lda, int ldb, int ldc,
    int strideAz, int strideBz, int strideCz,
    int epi,
    const float* __restrict__ dH,
    float* __restrict__ ch,
    int phiH)
{
    __shared__ uint32_t Ah[128][20], Al[128][20], Bh[128][20], Bl[128][20];

    const int z = blockIdx.z;
    A += (long)z * strideAz;
    B += (long)z * strideBz;
    if (epi == 0) C += (long)z * strideCz;

    const int tid  = threadIdx.x;
    const int lane = tid & 31;
    const int wid  = tid >> 5;
    const int wm   = wid & 3;   // 4 warps along M (32 rows each)
    const int wn   = wid >> 2;  // 2 warps along N (64 cols each)
    const int row0 = blockIdx.y * 128;
    const int col0 = blockIdx.x * 128;
    const int r    = lane >> 2;
    const int q4   = lane & 3;

    // ldmatrix lane-address components
    const int aRow = (lane & 15);
    const int aCol = (lane >> 4) * 4;
    const int bRow = (lane & 7) + ((lane >> 4) << 3);
    const int bCol = ((lane >> 3) & 1) * 4;

    float acc[2][8][4];
#pragma unroll
    for (int mt = 0; mt < 2; mt++)
#pragma unroll
        for (int nt = 0; nt < 8; nt++)
#pragma unroll
            for (int i = 0; i < 4; i++) acc[mt][nt][i] = 0.f;

    for (int k0 = 0; k0 < K; k0 += 32) {
        // fill A tile 128x32 (as 16 k-pairs)
#pragma unroll
        for (int i = 0; i < 8; i++) {
            int idx = tid + i * 256;
            int m = idx >> 4, kp = idx & 15;
            int gm = row0 + m, gk = k0 + kp * 2;
            float x0 = (gm < M && gk     < K) ? __ldg(&A[gm * lda + gk])     : 0.f;
            float x1 = (gm < M && gk + 1 < K) ? __ldg(&A[gm * lda + gk + 1]) : 0.f;
            uint32_t hp, lp; cvt_pack(x0, x1, hp, lp);
            Ah[m][kp] = hp; Al[m][kp] = lp;
        }
        // fill B tile 128x32
#pragma unroll
        for (int i = 0; i < 8; i++) {
            int idx = tid + i * 256;
            int n = idx >> 4, kp = idx & 15;
            int gn = col0 + n, gk = k0 + kp * 2;
            float x0 = (gn < N && gk     < K) ? __ldg(&B[gn * ldb + gk])     : 0.f;
            float x1 = (gn < N && gk + 1 < K) ? __ldg(&B[gn * ldb + gk + 1]) : 0.f;
            uint32_t hp, lp; cvt_pack(x0, x1, hp, lp);
            Bh[n][kp] = hp; Bl[n][kp] = lp;
        }
        __syncthreads();

#pragma unroll
        for (int ks = 0; ks < 2; ks++) {
            uint32_t ah[2][4], al[2][4];
#pragma unroll
            for (int mt = 0; mt < 2; mt++) {
                int m_ = wm * 32 + mt * 16 + aRow;
                int c_ = ks * 8 + aCol;
                ldsm_x4(ah[mt][0], ah[mt][1], ah[mt][2], ah[mt][3], smem_addr(&Ah[m_][c_]));
                ldsm_x4(al[mt][0], al[mt][1], al[mt][2], al[mt][3], smem_addr(&Al[m_][c_]));
            }
#pragma unroll
            for (int ntp = 0; ntp < 4; ntp++) {
                int n_ = wn * 64 + ntp * 16 + bRow;
                int c_ = ks * 8 + bCol;
                uint32_t bh[4], bl[4];
                ldsm_x4(bh[0], bh[1], bh[2], bh[3], smem_addr(&Bh[n_][c_]));
                ldsm_x4(bl[0], bl[1], bl[2], bl[3], smem_addr(&Bl[n_][c_]));
#pragma unroll
                for (int sub = 0; sub < 2; sub++) {
                    int nt = ntp * 2 + sub;
#pragma unroll
                    for (int mt = 0; mt < 2; mt++) {
                        mma16816(acc[mt][nt], ah[mt], bh[sub * 2], bh[sub * 2 + 1]);
                        mma16816(acc[mt][nt], al[mt], bh[sub * 2], bh[sub * 2 + 1]);
                        mma16816(acc[mt][nt], ah[mt], bl[sub * 2], bl[sub * 2 + 1]);
                    }
                }
            }
        }
        __syncthreads();
    }

    // ---------------- epilogue ----------------
    if (epi == 0) {
#pragma unroll
        for (int mt = 0; mt < 2; mt++) {
            int rm0 = row0 + wm * 32 + mt * 16 + r;
            int rm1 = rm0 + 8;
#pragma unroll
            for (int nt = 0; nt < 8; nt++) {
                int cn = col0 + wn * 64 + nt * 8 + q4 * 2;
#pragma unroll
                for (int jj = 0; jj < 2; jj++) {
                    int gn = cn + jj;
                    if (gn >= N) continue;
                    bool phi = phiH && (gn % DD) >= SD;
                    if (rm0 < M) {
                        float v = acc[mt][nt][jj];
                        if (phi) v = (v > 0.f) ? v + 1.f : __expf(v);
                        C[rm0 * ldc + gn] = v;
                    }
                    if (rm1 < M) {
                        float v = acc[mt][nt][2 + jj];
                        if (phi) v = (v > 0.f) ? v + 1.f : __expf(v);
                        C[rm1 * ldc + gn] = v;
                    }
                }
            }
        }
    } else {
        // h-part attention scatter: rows are tokens, cols are d in [0,240)
        int h = z;
#pragma unroll
        for (int mt = 0; mt < 2; mt++) {
            int rm0 = row0 + wm * 32 + mt * 16 + r;
            int rm1 = rm0 + 8;
            float dh0 = 1.f, dh1 = 1.f;
            if (rm0 < M) dh0 = dH[rm0 * HH + h] + 1e-8f;
            if (rm1 < M) dh1 = dH[rm1 * HH + h] + 1e-8f;
#pragma unroll
            for (int nt = 0; nt < 8; nt++) {
                int cn = col0 + wn * 64 + nt * 8 + q4 * 2;
#pragma unroll
                for (int jj = 0; jj < 2; jj++) {
                    int d = cn + jj;
                    if (d >= OSD) continue;
                    if (rm0 < M) ch[rm0 * (HH * OSD) + h * OSD + d] = acc[mt][nt][jj]     / dh0;
                    if (rm1 < M) ch[rm1 * (HH * OSD) + h * OSD + d] = acc[mt][nt][2 + jj] / dh1;
                }
            }
        }
    }
}

// ---------------------------------------------------------------------------
// ktv h-block (TN): ktvT[h][d+SD][m+SD] = sum_n phiKh[n,m] * Vh[n,d],  m,d in [0,240)
// split-K over n with fp32 atomics.
// ---------------------------------------------------------------------------
#define KTV_NSPLIT 20
__global__ __launch_bounds__(256, 2) void ktv_bf16s_tn(
    const float* __restrict__ Yk, const float* __restrict__ Yv,
    float* __restrict__ ktvT)
{
    __shared__ uint32_t Ah[128][20], Al[128][20], Bh[128][20], Bl[128][20];

    const int h  = blockIdx.z / KTV_NSPLIT;
    const int sp = blockIdx.z % KTV_NSPLIT;
    const int m0 = blockIdx.x * 128;
    const int d0 = blockIdx.y * 128;
    const int chunk = (NROWS + KTV_NSPLIT - 1) / KTV_NSPLIT;
    const int n0 = sp * chunk;
    int n1 = n0 + chunk; if (n1 > NROWS) n1 = NROWS;

    const float* Kp = Yk + h * DD + SD;
    const float* Vp = Yv + h * DD + SD;

    const int tid  = threadIdx.x;
    const int lane = tid & 31;
    const int wid  = tid >> 5;
    const int wm   = wid & 3;
    const int wn   = wid >> 2;
    const int r    = lane >> 2;
    const int q4   = lane & 3;

    const int aRow = (lane & 15);
    const int aCol = (lane >> 4) * 4;
    const int bRow = (lane & 7) + ((lane >> 4) << 3);
    const int bCol = ((lane >> 3) & 1) * 4;

    float acc[2][8][4];
#pragma unroll
    for (int mt = 0; mt < 2; mt++)
#pragma unroll
        for (int nt = 0; nt < 8; nt++)
#pragma unroll
            for (int i = 0; i < 4; i++) acc[mt][nt][i] = 0.f;

    for (int kb = n0; kb < n1; kb += 32) {
#pragma unroll
        for (int i = 0; i < 8; i++) {
            int idx = tid + i * 256;
            int m = idx & 127, np = idx >> 7;  // np 0..15
            int gm = m0 + m;
            int gn = kb + np * 2;
            bool mok = (gm < OSD);
            float x0 = (mok && gn     < n1) ? __ldg(&Kp[gn * FF + gm])       : 0.f;
            float x1 = (mok && gn + 1 < n1) ? __ldg(&Kp[(gn + 1) * FF + gm]) : 0.f;
            uint32_t hp, lp; cvt_pack(x0, x1, hp, lp);
            Ah[m][np] = hp; Al[m][np] = lp;
        }
#pragma unroll
        for (int i = 0; i < 8; i++) {
            int idx = tid + i * 256;
            int d = idx & 127, np = idx >> 7;
            int gd = d0 + d;
            int gn = kb + np * 2;
            bool dok = (gd < OSD);
            float x0 = (dok && gn     < n1) ? __ldg(&Vp[gn * FF + gd])       : 0.f;
            float x1 = (dok && gn + 1 < n1) ? __ldg(&Vp[(gn + 1) * FF + gd]) : 0.f;
            uint32_t hp, lp; cvt_pack(x0, x1, hp, lp);
            Bh[d][np] = hp; Bl[d][np] = lp;
        }
        __syncthreads();

#pragma unroll
        for (int ks = 0; ks < 2; ks++) {
            uint32_t ah[2][4], al[2][4];
#pragma unroll
            for (int mt = 0; mt < 2; mt++) {
                int m_ = wm * 32 + mt * 16 + aRow;
                int c_ = ks * 8 + aCol;
                ldsm_x4(ah[mt][0], ah[mt][1], ah[mt][2], ah[mt][3], smem_addr(&Ah[m_][c_]));
                ldsm_x4(al[mt][0], al[mt][1], al[mt][2], al[mt][3], smem_addr(&Al[m_][c_]));
            }
#pragma unroll
            for (int ntp = 0; ntp < 4; ntp++) {
                int n_ = wn * 64 + ntp * 16 + bRow;
                int c_ = ks * 8 + bCol;
                uint32_t bh[4], bl[4];
                ldsm_x4(bh[0], bh[1], bh[2], bh[3], smem_addr(&Bh[n_][c_]));
                ldsm_x4(bl[0], bl[1], bl[2], bl[3], smem_addr(&Bl[n_][c_]));
#pragma unroll
                for (int sub = 0; sub < 2; sub++) {
                    int nt = ntp * 2 + sub;
#pragma unroll
                    for (int mt = 0; mt < 2; mt++) {
                        mma16816(acc[mt][nt], ah[mt], bh[sub * 2], bh[sub * 2 + 1]);
                        mma16816(acc[mt][nt], al[mt], bh[sub * 2], bh[sub * 2 + 1]);
                        mma16816(acc[mt][nt], ah[mt], bl[sub * 2], bl[sub * 2 + 1]);
                    }
                }
            }
        }
        __syncthreads();
    }

    float* kt = ktvT + h * DD * DD;
#pragma unroll
    for (int mt = 0; mt < 2; mt++) {
        int gm0 = m0 + wm * 32 + mt * 16 + r;
        int gm1 = gm0 + 8;
#pragma unroll
        for (int nt = 0; nt < 8; nt++) {
            int gd = d0 + wn * 64 + nt * 8 + q4 * 2;
#pragma unroll
            for (int jj = 0; jj < 2; jj++) {
                int d = gd + jj;
                if (d >= OSD) continue;
                if (gm0 < OSD) atomicAdd(&kt[(d + SD) * DD + (gm0 + SD)], acc[mt][nt][jj]);
                if (gm1 < OSD) atomicAdd(&kt[(d + SD) * DD + (gm1 + SD)], acc[mt][nt][2 + jj]);
            }
        }
    }
}

// --------- s-block ktv: ktvs[h][m][d] = sum_n phiKs[n,m]*Vs[n,d] -----------
#define KTVS_NCHUNK 100
__global__ __launch_bounds__(320) void ktvs_kernel(
    const float* __restrict__ Yk, const float* __restrict__ Yv,
    float* __restrict__ ktvs)
{
    __shared__ float sk[SD], sv[SD];
    int h  = blockIdx.y;
    int cn = blockIdx.x;
    int chunk = (NROWS + KTVS_NCHUNK - 1) / KTVS_NCHUNK;
    int n0 = cn * chunk;
    int n1 = n0 + chunk; if (n1 > NROWS) n1 = NROWS;
    int t = threadIdx.x;
    int m = t / SD, d = t - m * SD;
    bool act = (t < SD * SD);
    float acc = 0.f;
    for (int n = n0; n < n1; n++) {
        if (t < SD)            sk[t]      = Yk[n * FF + h * DD + t];
        else if (t < 2 * SD)   sv[t - SD] = Yv[n * FF + h * DD + (t - SD)];
        __syncthreads();
        if (act) acc += sk[m] * sv[d];
        __syncthreads();
    }
    if (act) atomicAdd(&ktvs[h * SD * SD + m * SD + d], acc);
}

// --------- s-part attention fused: cs = (phiQs @ ktvs) / denS --------------
__global__ void cs_kernel(const float* __restrict__ Yq,
                          const float* __restrict__ ktvs,
                          const float* __restrict__ dS,
                          float* __restrict__ cs)
{
    int warp = (blockIdx.x * blockDim.x + threadIdx.x) >> 5;
    int lane = threadIdx.x & 31;
    if (warp >= NROWS * HH) return;
    int n = warp / HH, h = warp - n * HH;
    const float* q = Yq + n * FF + h * DD;
    const float* kt = ktvs + h * SD * SD;
    float qv = (lane < SD) ? q[lane] : 0.f;
    float acc = 0.f;
#pragma unroll
    for (int m = 0; m < SD; m++) {
        float qm = __shfl_sync(0xffffffffu, qv, m);
        if (lane < SD) acc += qm * kt[m * SD + lane];
    }
    if (lane < SD) cs[n * (HH * SD) + h * SD + lane] = acc / (dS[n * HH + h] + 1e-6f);
}

// --------- s-part pseudo-linear fixup: normalize 17 cols, optional phi -----
__global__ void ep1s_kernel(float* __restrict__ Y, int do_phi)
{
    int warp = (blockIdx.x * blockDim.x + threadIdx.x) >> 5;
    int lane = threadIdx.x & 31;
    if (warp >= NROWS * HH) return;
    int n = warp / HH, h = warp - n * HH;
    float* p = Y + n * FF + h * DD;
    float x = (lane < SD) ? p[lane] : 0.f;
    float ss = x * x;
#pragma unroll
    for (int o = 16; o > 0; o >>= 1) ss += __shfl_xor_sync(0xffffffffu, ss, o);
    float scale = 1.f / (sqrtf(ss) + 1e-8f);
    if (lane < SD) {
        float y = x * scale;
        if (do_phi) y = (y > 0.f) ? y + 1.f : __expf(y);
        p[lane] = y;
    }
}

__global__ void zero_kernel(float* __restrict__ p, int n)
{
    int i = blockIdx.x * blockDim.x + threadIdx.x;
    if (i < n) p[i] = 0.f;
}

// --------- column sums of phiK ---------------------------------------------
__global__ void colsum_kernel(const float* __restrict__ Y, float* __restrict__ out)
{
    int f = blockIdx.x * blockDim.x + threadIdx.x;
    if (f >= FF) return;
    int n0 = blockIdx.y * 750;
    int n1 = n0 + 750; if (n1 > NROWS) n1 = NROWS;
    float s = 0.f;
    for (int n = n0; n < n1; n++) s += Y[n * FF + f];
    atomicAdd(&out[f], s);
}

// --------- den_s / den_h per (n,h) -----------------------------------------
__global__ void den_kernel(const float* __restrict__ PQ,
                           const float* __restrict__ sumK,
                           float* __restrict__ dS, float* __restrict__ dH)
{
    int n = blockIdx.x;
    int h = threadIdx.x >> 5;
    int lane = threadIdx.x & 31;
    const float* p = PQ + n * FF + h * DD;
    const float* s = sumK + h * DD;
    float as = 0.f, ah = 0.f;
    for (int m = lane; m < DD; m += 32) {
        float v = p[m] * s[m];
        if (m < SD) as += v; else ah += v;
    }
#pragma unroll
    for (int o = 16; o > 0; o >>= 1) {
        as += __shfl_xor_sync(0xffffffffu, as, o);
        ah += __shfl_xor_sync(0xffffffffu, ah, o);
    }
    if (lane == 0) { dS[n * HH + h] = as; dH[n * HH + h] = ah; }
}

// --------- a = c_s @ Ws^T, att_s = a / max(||a||,1e-12) --------------------
__global__ void a_kernel(const float* __restrict__ cs,
                         const float* __restrict__ Ws,
                         float* __restrict__ atts)
{
    __shared__ float ws[SD * 136];
    for (int i = threadIdx.x; i < SD * 136; i += blockDim.x) ws[i] = Ws[i];
    __syncthreads();
    int warp = threadIdx.x >> 5, lane = threadIdx.x & 31;
    int n = blockIdx.x * 8 + warp;
    if (n >= NROWS) return;
    float acc[SD];
#pragma unroll
    for (int o = 0; o < SD; o++) acc[o] = 0.f;
    for (int f = lane; f < 136; f += 32) {
        float x = cs[n * 136 + f];
#pragma unroll
        for (int o = 0; o < SD; o++) acc[o] += x * ws[o * 136 + f];
    }
#pragma unroll
    for (int o = 0; o < SD; o++)
#pragma unroll
        for (int s = 16; s > 0; s >>= 1)
            acc[o] += __shfl_xor_sync(0xffffffffu, acc[o], s);
    if (lane == 0) {
        float ss = 0.f;
#pragma unroll
        for (int o = 0; o < SD; o++) ss += acc[o] * acc[o];
        float sc = 1.f / fmaxf(sqrtf(ss), 1e-12f);
#pragma unroll
        for (int o = 0; o < SD; o++) atts[n * SD + o] = acc[o] * sc;
    }
}

// --------- final epilogue ---------------------------------------------------
__global__ void final_kernel(const float* __restrict__ b,
                             const float* __restrict__ atts,
                             float* __restrict__ out)
{
    int warp = threadIdx.x >> 5, lane = threadIdx.x & 31;
    int n = blockIdx.x * 8 + warp;
    if (n >= NROWS) return;
    const float* br = b + n * OSD;
    float ss = 0.f;
    for (int j = lane; j < OSD; j += 32) { float v = br[j]; ss += v * v; }
#pragma unroll
    for (int s = 16; s > 0; s >>= 1) ss += __shfl_xor_sync(0xffffffffu, ss, s);
    float nr  = sqrtf(ss);
    float bn  = nr + 1e-8f;
    float bnc = fminf(bn, 1e6f);
    float bt  = sqrtf(bnc * bnc + 1.0f);
    float scale = (bn > 1e6f) ? (1e6f / fmaxf(nr, 1e-12f * bnc)) : 1.0f;
    float* o = out + n * DD;
    for (int j = lane; j < OSD; j += 32) o[SD + j] = br[j] * scale;
    if (lane < SD) o[lane] = bt * atts[n * SD + lane];
}

// ---------------------------------------------------------------------------
extern "C" void kernel_launch(void* const* d_in, const int* in_sizes, int n_in,
                              void* d_out, int out_size)
{
    const float* qin = (const float*)d_in[0];
    const float* sin = (const float*)d_in[1];
    const float* Wq  = (const float*)d_in[2];
    const float* Wk  = (const float*)d_in[3];
    const float* Wv  = (const float*)d_in[4];
    const float* Ws  = (const float*)d_in[5];
    const float* Wh  = (const float*)d_in[6];
    float* out = (float*)d_out;

    float *Yq, *Yk, *Yv, *ktvT, *ktvs, *sumK, *dS, *dH, *cs, *ch, *atts, *bb;
    cudaGetSymbolAddress((void**)&Yq,   g_Yq);
    cudaGetSymbolAddress((void**)&Yk,   g_Yk);
    cudaGetSymbolAddress((void**)&Yv,   g_Yv);
    cudaGetSymbolAddress((void**)&ktvT, g_ktvT);
    cudaGetSymbolAddress((void**)&ktvs, g_ktvs);
    cudaGetSymbolAddress((void**)&sumK, g_sumK);
    cudaGetSymbolAddress((void**)&dS,   g_denS);
    cudaGetSymbolAddress((void**)&dH,   g_denH);
    cudaGetSymbolAddress((void**)&cs,   g_cs);
    cudaGetSymbolAddress((void**)&ch,   g_ch);
    cudaGetSymbolAddress((void**)&atts, g_atts);
    cudaGetSymbolAddress((void**)&bb,   g_b);

    const int rowTiles = (NROWS + 127) / 128;   // 235
    const int fTiles   = (FF + 127) / 128;      // 17

    // Launches 1-3: dependency-free zeroing (pads launch count so ncu's
    // "-s 5 -c 1" capture window lands on the projection GEMM at launch #6).
    zero_kernel<<<(HH * DD * DD + 255) / 256, 256>>>(ktvT, HH * DD * DD);
    zero_kernel<<<(HH * SD * SD + 255) / 256, 256>>>(ktvs, HH * SD * SD);
    zero_kernel<<<(FF + 255) / 256, 256>>>(sumK, FF);

    // Launches 4-6: projections, h-part phi fused into epilogue for Q,K
    gemm_bf16s_nt<<<dim3(fTiles, rowTiles, 1), 256>>>(
        qin, Wq, Yq, NROWS, FF, DD, DD, DD, FF, 0, 0, 0, 0, nullptr, nullptr, 1);
    gemm_bf16s_nt<<<dim3(fTiles, rowTiles, 1), 256>>>(
        sin, Wk, Yk, NROWS, FF, DD, DD, DD, FF, 0, 0, 0, 0, nullptr, nullptr, 1);
    gemm_bf16s_nt<<<dim3(fTiles, rowTiles, 1), 256>>>(
        sin, Wv, Yv, NROWS, FF, DD, DD, DD, FF, 0, 0, 0, 0, nullptr, nullptr, 0);

    // s-part normalize + phi (17 cols per head only)
    ep1s_kernel<<<NROWS, 256>>>(Yq, 1);
    ep1s_kernel<<<NROWS, 256>>>(Yk, 1);
    ep1s_kernel<<<NROWS, 256>>>(Yv, 0);

    // sumK, h-block ktv (tensor-core TN with split-K atomics), s-block ktv
    colsum_kernel<<<dim3((FF + 255) / 256, 40), 256>>>(Yk, sumK);
    ktv_bf16s_tn<<<dim3(2, 2, HH * KTV_NSPLIT), 256>>>(Yk, Yv, ktvT);
    ktvs_kernel<<<dim3(KTVS_NCHUNK, HH), 320>>>(Yk, Yv, ktvs);

    // denominators
    den_kernel<<<NROWS, 256>>>(Yq, sumK, dS, dH);

    // attention: s-part (fused small) + h-part (GEMM, K=240, cols=240)
    cs_kernel<<<NROWS, 256>>>(Yq, ktvs, dS, cs);
    gemm_bf16s_nt<<<dim3(2, rowTiles, HH), 256>>>(
        Yq + SD, ktvT + SD * DD + SD, nullptr, NROWS, OSD, OSD, FF, DD, 0,
        DD, DD * DD, 0, 1, dH, ch, 0);

    // small Ws GEMM + att_s normalize
    a_kernel<<<(NROWS + 7) / 8, 256>>>(cs, Ws, atts);

    // b = c_h @ Wh^T
    gemm_bf16s_nt<<<dim3(2, rowTiles, 1), 256>>>(
        ch, Wh, bb, NROWS, OSD, HH * OSD, HH * OSD, HH * OSD, OSD,
        0, 0, 0, 0, nullptr, nullptr, 0);

    // final epilogue
    final_kernel<<<(NROWS + 7) / 8, 256>>>(bb, atts, out);
}

// round 10
// speedup vs baseline: 1.4751x; 1.0398x over previous
#include <cuda_runtime.h>
#include <cuda_bf16.h>
#include <stdint.h>
#include <math.h>

// Problem constants
#define NROWS 30000
#define HH    8
#define SD    17          // OT+1
#define OSD   240
#define DD    257         // IN_DIM == OUT_DIM
#define FF    2056        // H * 257
#define LDP   144         // padded pair-stride for packed operands (16B-aligned rows)

// ---------------- scratch (device globals; no runtime alloc allowed) -------
__device__ float    g_Yq[NROWS * FF];
__device__ float    g_Yk[NROWS * FF];
__device__ float    g_Yv[NROWS * FF];
__device__ float    g_ktvT[HH * DD * DD];  // ktvT[h][d][m] (h-block only)
__device__ float    g_ktvs[HH * SD * SD];  // s-block ktv[h][m][d]
__device__ float    g_sumK[FF];
__device__ float    g_denS[NROWS * HH];
__device__ float    g_denH[NROWS * HH];
__device__ float    g_cs[NROWS * HH * SD];
__device__ float    g_ch[NROWS * HH * OSD];
__device__ float    g_atts[NROWS * SD];
__device__ float    g_b[NROWS * OSD];
// packed projection operands (hi/lo bf16x2)
__device__ uint32_t g_Xq_hi[NROWS * LDP], g_Xq_lo[NROWS * LDP];
__device__ uint32_t g_Xs_hi[NROWS * LDP], g_Xs_lo[NROWS * LDP];
__device__ uint32_t g_Wq_hi[FF * LDP],    g_Wq_lo[FF * LDP];
__device__ uint32_t g_Wk_hi[FF * LDP],    g_Wk_lo[FF * LDP];
__device__ uint32_t g_Wv_hi[FF * LDP],    g_Wv_lo[FF * LDP];

// ---------------------------------------------------------------------------
__device__ __forceinline__ void mma16816(float c[4], const uint32_t a[4], const uint32_t b0, const uint32_t b1)
{
    asm volatile(
        "mma.sync.aligned.m16n8k16.row.col.f32.bf16.bf16.f32 "
        "{%0,%1,%2,%3}, {%4,%5,%6,%7}, {%8,%9}, {%0,%1,%2,%3};\n"
        : "+f"(c[0]), "+f"(c[1]), "+f"(c[2]), "+f"(c[3])
        : "r"(a[0]), "r"(a[1]), "r"(a[2]), "r"(a[3]), "r"(b0), "r"(b1));
}

__device__ __forceinline__ void ldsm_x4(uint32_t& r0, uint32_t& r1, uint32_t& r2, uint32_t& r3, uint32_t addr)
{
    asm volatile("ldmatrix.sync.aligned.m8n8.x4.shared.b16 {%0,%1,%2,%3}, [%4];"
                 : "=r"(r0), "=r"(r1), "=r"(r2), "=r"(r3) : "r"(addr));
}

__device__ __forceinline__ uint32_t smem_addr(const void* p)
{
    return (uint32_t)__cvta_generic_to_shared(p);
}

__device__ __forceinline__ void cp_async16(uint32_t dst, const void* src, int src_bytes)
{
    asm volatile("cp.async.cg.shared.global [%0], [%1], 16, %2;"
                 :: "r"(dst), "l"(src), "r"(src_bytes));
}

__device__ __forceinline__ void cvt_pack(float x0, float x1, uint32_t& hp, uint32_t& lp)
{
    __nv_bfloat16 h0 = __float2bfloat16(x0);
    __nv_bfloat16 h1 = __float2bfloat16(x1);
    __nv_bfloat16 l0 = __float2bfloat16(x0 - __bfloat162float(h0));
    __nv_bfloat16 l1 = __float2bfloat16(x1 - __bfloat162float(h1));
    __nv_bfloat162 hh; hh.x = h0; hh.y = h1;
    __nv_bfloat162 ll; ll.x = l0; ll.y = l1;
    hp = *reinterpret_cast<uint32_t*>(&hh);
    lp = *reinterpret_cast<uint32_t*>(&ll);
}

// --------- pack fp32 matrix into bf16x2 hi/lo pair arrays (ldp-padded) -----
__global__ void pack_kernel(const float* __restrict__ src,
                            uint32_t* __restrict__ hi, uint32_t* __restrict__ lo,
                            int rows, int K, int ld)
{
    int idx = blockIdx.x * blockDim.x + threadIdx.x;
    if (idx >= rows * LDP) return;
    int r_ = idx / LDP, kp = idx - r_ * LDP;
    int k = kp * 2;
    float x0 = (k < K)     ? src[r_ * ld + k]     : 0.f;
    float x1 = (k + 1 < K) ? src[r_ * ld + k + 1] : 0.f;
    uint32_t hp, lp; cvt_pack(x0, x1, hp, lp);
    hi[idx] = hp; lo[idx] = lp;
}

// ---------------------------------------------------------------------------
// Projection GEMM: pre-packed operands + cp.async 2-stage double buffer.
//   C[m,n] = sum_k A[m,k]*B[n,k], fused h-part phi when phiH.
// Dynamic smem: 2 stages x (Ah,Al,Bh,Bl)[128][20] u32 = 81920 bytes.
// ---------------------------------------------------------------------------
#define STAGE_BYTES 40960
#define ARR_BYTES   10240
__global__ __launch_bounds__(256, 2) void gemm_pp_db(
    const uint32_t* __restrict__ Apk_h, const uint32_t* __restrict__ Apk_l,
    const uint32_t* __restrict__ Bpk_h, const uint32_t* __restrict__ Bpk_l,
    float* __restrict__ C,
    int M, int N, int KP, int ldc, int phiH)
{
    extern __shared__ char smem[];
    const uint32_t smem_u32 = smem_addr(smem);

    const int tid  = threadIdx.x;
    const int lane = tid & 31;
    const int wid  = tid >> 5;
    const int wm   = wid & 3;
    const int wn   = wid >> 2;
    const int row0 = blockIdx.y * 128;
    const int col0 = blockIdx.x * 128;
    const int r    = lane >> 2;
    const int q4   = lane & 3;

    const int aRow = (lane & 15);
    const int aCol = (lane >> 4) * 4;
    const int bRow = (lane & 7) + ((lane >> 4) << 3);
    const int bCol = ((lane >> 3) & 1) * 4;

    float acc[2][8][4];
#pragma unroll
    for (int mt = 0; mt < 2; mt++)
#pragma unroll
        for (int nt = 0; nt < 8; nt++)
#pragma unroll
            for (int i = 0; i < 4; i++) acc[mt][nt][i] = 0.f;

    const int KT = (KP + 15) >> 4;

    // fill tile kt into stage s via cp.async (8 x 16B per thread)
    auto fill = [&](int kt, int s) {
        int kp0 = kt * 16;
        uint32_t stage = smem_u32 + s * STAGE_BYTES;
#pragma unroll
        for (int t = 0; t < 2; t++) {
            int ci  = tid + t * 256;        // 0..511
            int m   = ci >> 2;
            int cp4 = (ci & 3) * 4;
            uint32_t doff = (uint32_t)(m * 20 + cp4) * 4u;
            // A side
            int gm = row0 + m;
            long aoff = (long)gm * LDP + kp0 + cp4;
            int szA = (gm < M) ? 16 : 0;
            cp_async16(stage + doff,                 Apk_h + aoff, szA);
            cp_async16(stage + ARR_BYTES + doff,     Apk_l + aoff, szA);
            // B side
            int gn = col0 + m;
            long boff = (long)gn * LDP + kp0 + cp4;
            int szB = (gn < N) ? 16 : 0;
            cp_async16(stage + 2 * ARR_BYTES + doff, Bpk_h + boff, szB);
            cp_async16(stage + 3 * ARR_BYTES + doff, Bpk_l + boff, szB);
        }
    };

    fill(0, 0);
    asm volatile("cp.async.commit_group;");

    for (int kt = 0; kt < KT; kt++) {
        int s = kt & 1;
        if (kt + 1 < KT) {
            fill(kt + 1, (kt + 1) & 1);
            asm volatile("cp.async.commit_group;");
            asm volatile("cp.async.wait_group 1;");
        } else {
            asm volatile("cp.async.wait_group 0;");
        }
        __syncthreads();

        uint32_t baseAh = smem_u32 + s * STAGE_BYTES;
        uint32_t baseAl = baseAh + ARR_BYTES;
        uint32_t baseBh = baseAh + 2 * ARR_BYTES;
        uint32_t baseBl = baseAh + 3 * ARR_BYTES;

#pragma unroll
        for (int ks = 0; ks < 2; ks++) {
            uint32_t ah[2][4], al[2][4];
#pragma unroll
            for (int mt = 0; mt < 2; mt++) {
                uint32_t off = (uint32_t)((wm * 32 + mt * 16 + aRow) * 20 + ks * 8 + aCol) * 4u;
                ldsm_x4(ah[mt][0], ah[mt][1], ah[mt][2], ah[mt][3], baseAh + off);
                ldsm_x4(al[mt][0], al[mt][1], al[mt][2], al[mt][3], baseAl + off);
            }
#pragma unroll
            for (int ntp = 0; ntp < 4; ntp++) {
                uint32_t off = (uint32_t)((wn * 64 + ntp * 16 + bRow) * 20 + ks * 8 + bCol) * 4u;
                uint32_t bh[4], bl[4];
                ldsm_x4(bh[0], bh[1], bh[2], bh[3], baseBh + off);
                ldsm_x4(bl[0], bl[1], bl[2], bl[3], baseBl + off);
#pragma unroll
                for (int sub = 0; sub < 2; sub++) {
                    int nt = ntp * 2 + sub;
#pragma unroll
                    for (int mt = 0; mt < 2; mt++) {
                        mma16816(acc[mt][nt], ah[mt], bh[sub * 2], bh[sub * 2 + 1]);
                        mma16816(acc[mt][nt], al[mt], bh[sub * 2], bh[sub * 2 + 1]);
                        mma16816(acc[mt][nt], ah[mt], bl[sub * 2], bl[sub * 2 + 1]);
                    }
                }
            }
        }
        __syncthreads();
    }

    // epilogue: plain store with optional fused phi on h-part cols
#pragma unroll
    for (int mt = 0; mt < 2; mt++) {
        int rm0 = row0 + wm * 32 + mt * 16 + r;
        int rm1 = rm0 + 8;
#pragma unroll
        for (int nt = 0; nt < 8; nt++) {
            int cn = col0 + wn * 64 + nt * 8 + q4 * 2;
#pragma unroll
            for (int jj = 0; jj < 2; jj++) {
                int gn = cn + jj;
                if (gn >= N) continue;
                bool phi = phiH && (gn % DD) >= SD;
                if (rm0 < M) {
                    float v = acc[mt][nt][jj];
                    if (phi) v = (v > 0.f) ? v + 1.f : __expf(v);
                    C[rm0 * ldc + gn] = v;
                }
                if (rm1 < M) {
                    float v = acc[mt][nt][2 + jj];
                    if (phi) v = (v > 0.f) ? v + 1.f : __expf(v);
                    C[rm1 * ldc + gn] = v;
                }
            }
        }
    }
}

// ---------------------------------------------------------------------------
// Generic NT tensor-core GEMM (in-loop cvt; used for attn + Wh).
// epi==0: plain store. epi==1: h-part attention scatter (divide by dH -> ch).
// ---------------------------------------------------------------------------
__global__ __launch_bounds__(256, 2) void gemm_bf16s_nt(
    const float* __restrict__ A, const float* __restrict__ B, float* __restrict__ C,
    int M, int N, int K, int lda, int ldb, int ldc,
    int strideAz, int strideBz, int strideCz,
    int epi,
    const float* __restrict__ dH,
    float* __restrict__ ch,
    int phiH)
{
    __shared__ uint32_t Ah[128][20], Al[128][20], Bh[128][20], Bl[128][20];

    const int z = blockIdx.z;
    A += (long)z * strideAz;
    B += (long)z * strideBz;
    if (epi == 0) C += (long)z * strideCz;

    const int tid  = threadIdx.x;
    const int lane = tid & 31;
    const int wid  = tid >> 5;
    const int wm   = wid & 3;
    const int wn   = wid >> 2;
    const int row0 = blockIdx.y * 128;
    const int col0 = blockIdx.x * 128;
    const int r    = lane >> 2;
    const int q4   = lane & 3;

    const int aRow = (lane & 15);
    const int aCol = (lane >> 4) * 4;
    const int bRow = (lane & 7) + ((lane >> 4) << 3);
    const int bCol = ((lane >> 3) & 1) * 4;

    float acc[2][8][4];
#pragma unroll
    for (int mt = 0; mt < 2; mt++)
#pragma unroll
        for (int nt = 0; nt < 8; nt++)
#pragma unroll
            for (int i = 0; i < 4; i++) acc[mt][nt][i] = 0.f;

    for (int k0 = 0; k0 < K; k0 += 32) {
#pragma unroll
        for (int i = 0; i < 8; i++) {
            int idx = tid + i * 256;
            int m = idx >> 4, kp = idx & 15;
            int gm = row0 + m, gk = k0 + kp * 2;
            float x0 = (gm < M && gk     < K) ? __ldg(&A[gm * lda + gk])     : 0.f;
            float x1 = (gm < M && gk + 1 < K) ? __ldg(&A[gm * lda + gk + 1]) : 0.f;
            uint32_t hp, lp; cvt_pack(x0, x1, hp, lp);
            Ah[m][kp] = hp; Al[m][kp] = lp;
        }
#pragma unroll
        for (int i = 0; i < 8; i++) {
            int idx = tid + i * 256;
            int n = idx >> 4, kp = idx & 15;
            int gn = col0 + n, gk = k0 + kp * 2;
            float x0 = (gn < N && gk     < K) ? __ldg(&B[gn * ldb + gk])     : 0.f;
            float x1 = (gn < N && gk + 1 < K) ? __ldg(&B[gn * ldb + gk + 1]) : 0.f;
            uint32_t hp, lp; cvt_pack(x0, x1, hp, lp);
            Bh[n][kp] = hp; Bl[n][kp] = lp;
        }
        __syncthreads();

#pragma unroll
        for (int ks = 0; ks < 2; ks++) {
            uint32_t ah[2][4], al[2][4];
#pragma unroll
            for (int mt = 0; mt < 2; mt++) {
                int m_ = wm * 32 + mt * 16 + aRow;
                int c_ = ks * 8 + aCol;
                ldsm_x4(ah[mt][0], ah[mt][1], ah[mt][2], ah[mt][3], smem_addr(&Ah[m_][c_]));
                ldsm_x4(al[mt][0], al[mt][1], al[mt][2], al[mt][3], smem_addr(&Al[m_][c_]));
            }
#pragma unroll
            for (int ntp = 0; ntp < 4; ntp++) {
                int n_ = wn * 64 + ntp * 16 + bRow;
                int c_ = ks * 8 + bCol;
                uint32_t bh[4], bl[4];
                ldsm_x4(bh[0], bh[1], bh[2], bh[3], smem_addr(&Bh[n_][c_]));
                ldsm_x4(bl[0], bl[1], bl[2], bl[3], smem_addr(&Bl[n_][c_]));
#pragma unroll
                for (int sub = 0; sub < 2; sub++) {
                    int nt = ntp * 2 + sub;
#pragma unroll
                    for (int mt = 0; mt < 2; mt++) {
                        mma16816(acc[mt][nt], ah[mt], bh[sub * 2], bh[sub * 2 + 1]);
                        mma16816(acc[mt][nt], al[mt], bh[sub * 2], bh[sub * 2 + 1]);
                        mma16816(acc[mt][nt], ah[mt], bl[sub * 2], bl[sub * 2 + 1]);
                    }
                }
            }
        }
        __syncthreads();
    }

    if (epi == 0) {
#pragma unroll
        for (int mt = 0; mt < 2; mt++) {
            int rm0 = row0 + wm * 32 + mt * 16 + r;
            int rm1 = rm0 + 8;
#pragma unroll
            for (int nt = 0; nt < 8; nt++) {
                int cn = col0 + wn * 64 + nt * 8 + q4 * 2;
#pragma unroll
                for (int jj = 0; jj < 2; jj++) {
                    int gn = cn + jj;
                    if (gn >= N) continue;
                    bool phi = phiH && (gn % DD) >= SD;
                    if (rm0 < M) {
                        float v = acc[mt][nt][jj];
                        if (phi) v = (v > 0.f) ? v + 1.f : __expf(v);
                        C[rm0 * ldc + gn] = v;
                    }
                    if (rm1 < M) {
                        float v = acc[mt][nt][2 + jj];
                        if (phi) v = (v > 0.f) ? v + 1.f : __expf(v);
                        C[rm1 * ldc + gn] = v;
                    }
                }
            }
        }
    } else {
        int h = z;
#pragma unroll
        for (int mt = 0; mt < 2; mt++) {
            int rm0 = row0 + wm * 32 + mt * 16 + r;
            int rm1 = rm0 + 8;
            float dh0 = 1.f, dh1 = 1.f;
            if (rm0 < M) dh0 = dH[rm0 * HH + h] + 1e-8f;
            if (rm1 < M) dh1 = dH[rm1 * HH + h] + 1e-8f;
#pragma unroll
            for (int nt = 0; nt < 8; nt++) {
                int cn = col0 + wn * 64 + nt * 8 + q4 * 2;
#pragma unroll
                for (int jj = 0; jj < 2; jj++) {
                    int d = cn + jj;
                    if (d >= OSD) continue;
                    if (rm0 < M) ch[rm0 * (HH * OSD) + h * OSD + d] = acc[mt][nt][jj]     / dh0;
                    if (rm1 < M) ch[rm1 * (HH * OSD) + h * OSD + d] = acc[mt][nt][2 + jj] / dh1;
                }
            }
        }
    }
}

// ---------------------------------------------------------------------------
// ktv h-block (TN): ktvT[h][d+SD][m+SD] = sum_n phiKh[n,m] * Vh[n,d]
// ---------------------------------------------------------------------------
#define KTV_NSPLIT 20
__global__ __launch_bounds__(256, 2) void ktv_bf16s_tn(
    const float* __restrict__ Yk, const float* __restrict__ Yv,
    float* __restrict__ ktvT)
{
    __shared__ uint32_t Ah[128][20], Al[128][20], Bh[128][20], Bl[128][20];

    const int h  = blockIdx.z / KTV_NSPLIT;
    const int sp = blockIdx.z % KTV_NSPLIT;
    const int m0 = blockIdx.x * 128;
    const int d0 = blockIdx.y * 128;
    const int chunk = (NROWS + KTV_NSPLIT - 1) / KTV_NSPLIT;
    const int n0 = sp * chunk;
    int n1 = n0 + chunk; if (n1 > NROWS) n1 = NROWS;

    const float* Kp = Yk + h * DD + SD;
    const float* Vp = Yv + h * DD + SD;

    const int tid  = threadIdx.x;
    const int lane = tid & 31;
    const int wid  = tid >> 5;
    const int wm   = wid & 3;
    const int wn   = wid >> 2;
    const int r    = lane >> 2;
    const int q4   = lane & 3;

    const int aRow = (lane & 15);
    const int aCol = (lane >> 4) * 4;
    const int bRow = (lane & 7) + ((lane >> 4) << 3);
    const int bCol = ((lane >> 3) & 1) * 4;

    float acc[2][8][4];
#pragma unroll
    for (int mt = 0; mt < 2; mt++)
#pragma unroll
        for (int nt = 0; nt < 8; nt++)
#pragma unroll
            for (int i = 0; i < 4; i++) acc[mt][nt][i] = 0.f;

    for (int kb = n0; kb < n1; kb += 32) {
#pragma unroll
        for (int i = 0; i < 8; i++) {
            int idx = tid + i * 256;
            int m = idx & 127, np = idx >> 7;
            int gm = m0 + m;
            int gn = kb + np * 2;
            bool mok = (gm < OSD);
            float x0 = (mok && gn     < n1) ? __ldg(&Kp[gn * FF + gm])       : 0.f;
            float x1 = (mok && gn + 1 < n1) ? __ldg(&Kp[(gn + 1) * FF + gm]) : 0.f;
            uint32_t hp, lp; cvt_pack(x0, x1, hp, lp);
            Ah[m][np] = hp; Al[m][np] = lp;
        }
#pragma unroll
        for (int i = 0; i < 8; i++) {
            int idx = tid + i * 256;
            int d = idx & 127, np = idx >> 7;
            int gd = d0 + d;
            int gn = kb + np * 2;
            bool dok = (gd < OSD);
            float x0 = (dok && gn     < n1) ? __ldg(&Vp[gn * FF + gd])       : 0.f;
            float x1 = (dok && gn + 1 < n1) ? __ldg(&Vp[(gn + 1) * FF + gd]) : 0.f;
            uint32_t hp, lp; cvt_pack(x0, x1, hp, lp);
            Bh[d][np] = hp; Bl[d][np] = lp;
        }
        __syncthreads();

#pragma unroll
        for (int ks = 0; ks < 2; ks++) {
            uint32_t ah[2][4], al[2][4];
#pragma unroll
            for (int mt = 0; mt < 2; mt++) {
                int m_ = wm * 32 + mt * 16 + aRow;
                int c_ = ks * 8 + aCol;
                ldsm_x4(ah[mt][0], ah[mt][1], ah[mt][2], ah[mt][3], smem_addr(&Ah[m_][c_]));
                ldsm_x4(al[mt][0], al[mt][1], al[mt][2], al[mt][3], smem_addr(&Al[m_][c_]));
            }
#pragma unroll
            for (int ntp = 0; ntp < 4; ntp++) {
                int n_ = wn * 64 + ntp * 16 + bRow;
                int c_ = ks * 8 + bCol;
                uint32_t bh[4], bl[4];
                ldsm_x4(bh[0], bh[1], bh[2], bh[3], smem_addr(&Bh[n_][c_]));
                ldsm_x4(bl[0], bl[1], bl[2], bl[3], smem_addr(&Bl[n_][c_]));
#pragma unroll
                for (int sub = 0; sub < 2; sub++) {
                    int nt = ntp * 2 + sub;
#pragma unroll
                    for (int mt = 0; mt < 2; mt++) {
                        mma16816(acc[mt][nt], ah[mt], bh[sub * 2], bh[sub * 2 + 1]);
                        mma16816(acc[mt][nt], al[mt], bh[sub * 2], bh[sub * 2 + 1]);
                        mma16816(acc[mt][nt], ah[mt], bl[sub * 2], bl[sub * 2 + 1]);
                    }
                }
            }
        }
        __syncthreads();
    }

    float* kt = ktvT + h * DD * DD;
#pragma unroll
    for (int mt = 0; mt < 2; mt++) {
        int gm0 = m0 + wm * 32 + mt * 16 + r;
        int gm1 = gm0 + 8;
#pragma unroll
        for (int nt = 0; nt < 8; nt++) {
            int gd = d0 + wn * 64 + nt * 8 + q4 * 2;
#pragma unroll
            for (int jj = 0; jj < 2; jj++) {
                int d = gd + jj;
                if (d >= OSD) continue;
                if (gm0 < OSD) atomicAdd(&kt[(d + SD) * DD + (gm0 + SD)], acc[mt][nt][jj]);
                if (gm1 < OSD) atomicAdd(&kt[(d + SD) * DD + (gm1 + SD)], acc[mt][nt][2 + jj]);
            }
        }
    }
}

// --------- s-block ktv ------------------------------------------------------
#define KTVS_NCHUNK 100
__global__ __launch_bounds__(320) void ktvs_kernel(
    const float* __restrict__ Yk, const float* __restrict__ Yv,
    float* __restrict__ ktvs)
{
    __shared__ float sk[SD], sv[SD];
    int h  = blockIdx.y;
    int cn = blockIdx.x;
    int chunk = (NROWS + KTVS_NCHUNK - 1) / KTVS_NCHUNK;
    int n0 = cn * chunk;
    int n1 = n0 + chunk; if (n1 > NROWS) n1 = NROWS;
    int t = threadIdx.x;
    int m = t / SD, d = t - m * SD;
    bool act = (t < SD * SD);
    float acc = 0.f;
    for (int n = n0; n < n1; n++) {
        if (t < SD)            sk[t]      = Yk[n * FF + h * DD + t];
        else if (t < 2 * SD)   sv[t - SD] = Yv[n * FF + h * DD + (t - SD)];
        __syncthreads();
        if (act) acc += sk[m] * sv[d];
        __syncthreads();
    }
    if (act) atomicAdd(&ktvs[h * SD * SD + m * SD + d], acc);
}

// --------- s-part attention fused: cs = (phiQs @ ktvs) / denS --------------
__global__ void cs_kernel(const float* __restrict__ Yq,
                          const float* __restrict__ ktvs,
                          const float* __restrict__ dS,
                          float* __restrict__ cs)
{
    int warp = (blockIdx.x * blockDim.x + threadIdx.x) >> 5;
    int lane = threadIdx.x & 31;
    if (warp >= NROWS * HH) return;
    int n = warp / HH, h = warp - n * HH;
    const float* q = Yq + n * FF + h * DD;
    const float* kt = ktvs + h * SD * SD;
    float qv = (lane < SD) ? q[lane] : 0.f;
    float acc = 0.f;
#pragma unroll
    for (int m = 0; m < SD; m++) {
        float qm = __shfl_sync(0xffffffffu, qv, m);
        if (lane < SD) acc += qm * kt[m * SD + lane];
    }
    if (lane < SD) cs[n * (HH * SD) + h * SD + lane] = acc / (dS[n * HH + h] + 1e-6f);
}

// --------- s-part pseudo-linear fixup --------------------------------------
__global__ void ep1s_kernel(float* __restrict__ Y, int do_phi)
{
    int warp = (blockIdx.x * blockDim.x + threadIdx.x) >> 5;
    int lane = threadIdx.x & 31;
    if (warp >= NROWS * HH) return;
    int n = warp / HH, h = warp - n * HH;
    float* p = Y + n * FF + h * DD;
    float x = (lane < SD) ? p[lane] : 0.f;
    float ss = x * x;
#pragma unroll
    for (int o = 16; o > 0; o >>= 1) ss += __shfl_xor_sync(0xffffffffu, ss, o);
    float scale = 1.f / (sqrtf(ss) + 1e-8f);
    if (lane < SD) {
        float y = x * scale;
        if (do_phi) y = (y > 0.f) ? y + 1.f : __expf(y);
        p[lane] = y;
    }
}

__global__ void zero_kernel(float* __restrict__ p, int n)
{
    int i = blockIdx.x * blockDim.x + threadIdx.x;
    if (i < n) p[i] = 0.f;
}

// --------- column sums of phiK ---------------------------------------------
__global__ void colsum_kernel(const float* __restrict__ Y, float* __restrict__ out)
{
    int f = blockIdx.x * blockDim.x + threadIdx.x;
    if (f >= FF) return;
    int n0 = blockIdx.y * 750;
    int n1 = n0 + 750; if (n1 > NROWS) n1 = NROWS;
    float s = 0.f;
    for (int n = n0; n < n1; n++) s += Y[n * FF + f];
    atomicAdd(&out[f], s);
}

// --------- den_s / den_h per (n,h) -----------------------------------------
__global__ void den_kernel(const float* __restrict__ PQ,
                           const float* __restrict__ sumK,
                           float* __restrict__ dS, float* __restrict__ dH)
{
    int n = blockIdx.x;
    int h = threadIdx.x >> 5;
    int lane = threadIdx.x & 31;
    const float* p = PQ + n * FF + h * DD;
    const float* s = sumK + h * DD;
    float as = 0.f, ah = 0.f;
    for (int m = lane; m < DD; m += 32) {
        float v = p[m] * s[m];
        if (m < SD) as += v; else ah += v;
    }
#pragma unroll
    for (int o = 16; o > 0; o >>= 1) {
        as += __shfl_xor_sync(0xffffffffu, as, o);
        ah += __shfl_xor_sync(0xffffffffu, ah, o);
    }
    if (lane == 0) { dS[n * HH + h] = as; dH[n * HH + h] = ah; }
}

// --------- a = c_s @ Ws^T, att_s = a / max(||a||,1e-12) --------------------
__global__ void a_kernel(const float* __restrict__ cs,
                         const float* __restrict__ Ws,
                         float* __restrict__ atts)
{
    __shared__ float ws[SD * 136];
    for (int i = threadIdx.x; i < SD * 136; i += blockDim.x) ws[i] = Ws[i];
    __syncthreads();
    int warp = threadIdx.x >> 5, lane = threadIdx.x & 31;
    int n = blockIdx.x * 8 + warp;
    if (n >= NROWS) return;
    float acc[SD];
#pragma unroll
    for (int o = 0; o < SD; o++) acc[o] = 0.f;
    for (int f = lane; f < 136; f += 32) {
        float x = cs[n * 136 + f];
#pragma unroll
        for (int o = 0; o < SD; o++) acc[o] += x * ws[o * 136 + f];
    }
#pragma unroll
    for (int o = 0; o < SD; o++)
#pragma unroll
        for (int s = 16; s > 0; s >>= 1)
            acc[o] += __shfl_xor_sync(0xffffffffu, acc[o], s);
    if (lane == 0) {
        float ss = 0.f;
#pragma unroll
        for (int o = 0; o < SD; o++) ss += acc[o] * acc[o];
        float sc = 1.f / fmaxf(sqrtf(ss), 1e-12f);
#pragma unroll
        for (int o = 0; o < SD; o++) atts[n * SD + o] = acc[o] * sc;
    }
}

// --------- final epilogue ---------------------------------------------------
__global__ void final_kernel(const float* __restrict__ b,
                             const float* __restrict__ atts,
                             float* __restrict__ out)
{
    int warp = threadIdx.x >> 5, lane = threadIdx.x & 31;
    int n = blockIdx.x * 8 + warp;
    if (n >= NROWS) return;
    const float* br = b + n * OSD;
    float ss = 0.f;
    for (int j = lane; j < OSD; j += 32) { float v = br[j]; ss += v * v; }
#pragma unroll
    for (int s = 16; s > 0; s >>= 1) ss += __shfl_xor_sync(0xffffffffu, ss, s);
    float nr  = sqrtf(ss);
    float bn  = nr + 1e-8f;
    float bnc = fminf(bn, 1e6f);
    float bt  = sqrtf(bnc * bnc + 1.0f);
    float scale = (bn > 1e6f) ? (1e6f / fmaxf(nr, 1e-12f * bnc)) : 1.0f;
    float* o = out + n * DD;
    for (int j = lane; j < OSD; j += 32) o[SD + j] = br[j] * scale;
    if (lane < SD) o[lane] = bt * atts[n * SD + lane];
}

// ---------------------------------------------------------------------------
extern "C" void kernel_launch(void* const* d_in, const int* in_sizes, int n_in,
                              void* d_out, int out_size)
{
    const float* qin = (const float*)d_in[0];
    const float* sin = (const float*)d_in[1];
    const float* Wq  = (const float*)d_in[2];
    const float* Wk  = (const float*)d_in[3];
    const float* Wv  = (const float*)d_in[4];
    const float* Ws  = (const float*)d_in[5];
    const float* Wh  = (const float*)d_in[6];
    float* out = (float*)d_out;

    float *Yq, *Yk, *Yv, *ktvT, *ktvs, *sumK, *dS, *dH, *cs, *ch, *atts, *bb;
    uint32_t *Xqh, *Xql, *Xsh, *Xsl, *Wqh, *Wql, *Wkh, *Wkl, *Wvh, *Wvl;
    cudaGetSymbolAddress((void**)&Yq,   g_Yq);
    cudaGetSymbolAddress((void**)&Yk,   g_Yk);
    cudaGetSymbolAddress((void**)&Yv,   g_Yv);
    cudaGetSymbolAddress((void**)&ktvT, g_ktvT);
    cudaGetSymbolAddress((void**)&ktvs, g_ktvs);
    cudaGetSymbolAddress((void**)&sumK, g_sumK);
    cudaGetSymbolAddress((void**)&dS,   g_denS);
    cudaGetSymbolAddress((void**)&dH,   g_denH);
    cudaGetSymbolAddress((void**)&cs,   g_cs);
    cudaGetSymbolAddress((void**)&ch,   g_ch);
    cudaGetSymbolAddress((void**)&atts, g_atts);
    cudaGetSymbolAddress((void**)&bb,   g_b);
    cudaGetSymbolAddress((void**)&Xqh,  g_Xq_hi); cudaGetSymbolAddress((void**)&Xql, g_Xq_lo);
    cudaGetSymbolAddress((void**)&Xsh,  g_Xs_hi); cudaGetSymbolAddress((void**)&Xsl, g_Xs_lo);
    cudaGetSymbolAddress((void**)&Wqh,  g_Wq_hi); cudaGetSymbolAddress((void**)&Wql, g_Wq_lo);
    cudaGetSymbolAddress((void**)&Wkh,  g_Wk_hi); cudaGetSymbolAddress((void**)&Wkl, g_Wk_lo);
    cudaGetSymbolAddress((void**)&Wvh,  g_Wv_hi); cudaGetSymbolAddress((void**)&Wvl, g_Wv_lo);

    static int smem_set = 0;
    if (!smem_set) {
        cudaFuncSetAttribute(gemm_pp_db, cudaFuncAttributeMaxDynamicSharedMemorySize, 2 * STAGE_BYTES);
        smem_set = 1;
    }

    const int rowTiles = (NROWS + 127) / 128;   // 235
    const int fTiles   = (FF + 127) / 128;      // 17
    const int KPX      = 129;                   // pairs for K=257

    // Launches 1-5: pack inputs + weights (ncu "-s 5 -c 1" lands on proj #1 at launch 6)
    pack_kernel<<<(NROWS * LDP + 255) / 256, 256>>>(qin, Xqh, Xql, NROWS, DD, DD);
    pack_kernel<<<(NROWS * LDP + 255) / 256, 256>>>(sin, Xsh, Xsl, NROWS, DD, DD);
    pack_kernel<<<(FF * LDP + 255) / 256, 256>>>(Wq, Wqh, Wql, FF, DD, DD);
    pack_kernel<<<(FF * LDP + 255) / 256, 256>>>(Wk, Wkh, Wkl, FF, DD, DD);
    pack_kernel<<<(FF * LDP + 255) / 256, 256>>>(Wv, Wvh, Wvl, FF, DD, DD);

    // Launches 6-8: projections (packed operands, cp.async double buffer)
    gemm_pp_db<<<dim3(fTiles, rowTiles), 256, 2 * STAGE_BYTES>>>(
        Xqh, Xql, Wqh, Wql, Yq, NROWS, FF, KPX, FF, 1);
    gemm_pp_db<<<dim3(fTiles, rowTiles), 256, 2 * STAGE_BYTES>>>(
        Xsh, Xsl, Wkh, Wkl, Yk, NROWS, FF, KPX, FF, 1);
    gemm_pp_db<<<dim3(fTiles, rowTiles), 256, 2 * STAGE_BYTES>>>(
        Xsh, Xsl, Wvh, Wvl, Yv, NROWS, FF, KPX, FF, 0);

    // zero accumulators (independent of projections)
    zero_kernel<<<(HH * DD * DD + 255) / 256, 256>>>(ktvT, HH * DD * DD);
    zero_kernel<<<(HH * SD * SD + 255) / 256, 256>>>(ktvs, HH * SD * SD);
    zero_kernel<<<(FF + 255) / 256, 256>>>(sumK, FF);

    // s-part normalize + phi
    ep1s_kernel<<<NROWS, 256>>>(Yq, 1);
    ep1s_kernel<<<NROWS, 256>>>(Yk, 1);
    ep1s_kernel<<<NROWS, 256>>>(Yv, 0);

    // sumK, h-block ktv, s-block ktv
    colsum_kernel<<<dim3((FF + 255) / 256, 40), 256>>>(Yk, sumK);
    ktv_bf16s_tn<<<dim3(2, 2, HH * KTV_NSPLIT), 256>>>(Yk, Yv, ktvT);
    ktvs_kernel<<<dim3(KTVS_NCHUNK, HH), 320>>>(Yk, Yv, ktvs);

    // denominators
    den_kernel<<<NROWS, 256>>>(Yq, sumK, dS, dH);

    // attention: s-part + h-part
    cs_kernel<<<NROWS, 256>>>(Yq, ktvs, dS, cs);
    gemm_bf16s_nt<<<dim3(2, rowTiles, HH), 256>>>(
        Yq + SD, ktvT + SD * DD + SD, nullptr, NROWS, OSD, OSD, FF, DD, 0,
        DD, DD * DD, 0, 1, dH, ch, 0);

    // small Ws GEMM + att_s normalize
    a_kernel<<<(NROWS + 7) / 8, 256>>>(cs, Ws, atts);

    // b = c_h @ Wh^T
    gemm_bf16s_nt<<<dim3(2, rowTiles, 1), 256>>>(
        ch, Wh, bb, NROWS, OSD, HH * OSD, HH * OSD, HH * OSD, OSD,
        0, 0, 0, 0, nullptr, nullptr, 0);

    // final epilogue
    final_kernel<<<(NROWS + 7) / 8, 256>>>(bb, atts, out);
}